// round 8
// baseline (speedup 1.0000x reference)
#include <cuda_runtime.h>
#include <cuda_bf16.h>
#include <cstdint>

#define BB 4
#define CC 16
#define KK 16
#define HWHW (512 * 512)          // 262144
#define CHUNK 128                 // pixels per stage
#define NCHUNK (HWHW / CHUNK)     // 2048
#define GRIDX 148                 // 148*4 = 592 blocks = 4/SM, single wave
#define NTH 128
#define KPW 4                     // k's per warp (4 warps x 4 = 16)
#define CPH 8                     // channels per half-warp
#define NSTAGE 3

#define EMB_STAGE_FLOATS (CC * CHUNK)       // 2048 floats = 8 KB
#define MSK_STAGE_INTS   (KK * CHUNK)       // 2048 ints   = 8 KB
#define STAGE_BYTES (EMB_STAGE_FLOATS * 4 + MSK_STAGE_INTS * 4)   // 16 KB
#define SMEM_BYTES (NSTAGE * STAGE_BYTES)   // 48 KB -> 4 blocks/SM

// stats per (b,k): [0..15] channel sums, [16] sum ||e||^2 over fg, [17] count
__device__ float g_stats[BB][KK][18];   // zeroed at load; re-zeroed by last block each launch
__device__ unsigned int g_done;

// ---------------- f32x2 helpers ----------------
__device__ __forceinline__ unsigned long long pack2(float lo, float hi) {
    unsigned long long r;
    asm("mov.b64 %0, {%1, %2};" : "=l"(r) : "f"(lo), "f"(hi));
    return r;
}
__device__ __forceinline__ void fma2(unsigned long long& acc, unsigned long long a, unsigned long long b) {
    asm("fma.rn.f32x2 %0, %1, %2, %3;" : "=l"(acc) : "l"(a), "l"(b), "l"(acc));
}
__device__ __forceinline__ void add2(unsigned long long& acc, unsigned long long a) {
    asm("add.rn.f32x2 %0, %1, %2;" : "=l"(acc) : "l"(acc), "l"(a));
}
__device__ __forceinline__ float unpack_sum(unsigned long long v) {
    float lo, hi;
    asm("mov.b64 {%0, %1}, %2;" : "=f"(lo), "=f"(hi) : "l"(v));
    return lo + hi;
}
__device__ __forceinline__ float warp_sum(float x) {
#pragma unroll
    for (int off = 16; off > 0; off >>= 1)
        x += __shfl_down_sync(0xffffffffu, x, off);
    return x;
}
// reduce a packed f32x2 within a 16-lane half-warp, return lo+hi on half-lane 0
__device__ __forceinline__ float half_sum_pk(unsigned long long v) {
#pragma unroll
    for (int off = 8; off > 0; off >>= 1) {
        unsigned long long o = __shfl_down_sync(0xffffffffu, v, off, 16);
        add2(v, o);
    }
    return unpack_sum(v);
}
__device__ __forceinline__ void cp_async16(uint32_t dst_smem, const void* src) {
    asm volatile("cp.async.cg.shared.global [%0], [%1], 16;" :: "r"(dst_smem), "l"(src) : "memory");
}

// ---------------- fused kernel ----------------
__global__ __launch_bounds__(NTH, 4)
void stats_kernel(const float* __restrict__ emb, const int* __restrict__ mask,
                  float* __restrict__ out) {
    extern __shared__ char smraw[];

    const int b   = blockIdx.y;
    const int bx  = blockIdx.x;
    const int tid = threadIdx.x;
    const int w   = tid >> 5;        // warp = k-group
    const int l   = tid & 31;
    const int h   = l >> 4;          // half-warp: 0 -> channels 0..7, 1 -> 8..15
    const int hl  = l & 15;          // lane within half
    const int c0  = h * CPH;

    const float* embB = emb  + (size_t)b * CC * HWHW;
    const int*   mskB = mask + (size_t)b * KK * HWHW;

    // f32x2 accumulators: warp's 4 k's x this half's 8 channels
    unsigned long long acc2[KPW][CPH];
    unsigned long long ssq2[KPW], cnt2[KPW];
#pragma unroll
    for (int kk = 0; kk < KPW; ++kk) {
#pragma unroll
        for (int c = 0; c < CPH; ++c) acc2[kk][c] = 0ull;
        ssq2[kk] = 0ull; cnt2[kk] = 0ull;
    }

    // per stage: 512 emb + 512 mask 16B units -> 8 cp.async per thread
    auto prefetch = [&](int stage, int ch) {
        if (ch < NCHUNK) {
            const int pix0 = ch * CHUNK;
            uint32_t se = (uint32_t)__cvta_generic_to_shared(smraw + stage * STAGE_BYTES);
            uint32_t sk = se + EMB_STAGE_FLOATS * 4;
#pragma unroll
            for (int j = 0; j < 4; ++j) {
                int u   = tid + j * NTH;        // 0..511
                int c   = u >> 5;               // channel (32 16B units per row)
                int off = (u & 31) << 2;        // float offset within row
                cp_async16(se + (uint32_t)(c * CHUNK + off) * 4,
                           embB + (size_t)c * HWHW + pix0 + off);
            }
#pragma unroll
            for (int j = 0; j < 4; ++j) {
                int u   = tid + j * NTH;
                int k   = u >> 5;
                int off = (u & 31) << 2;
                cp_async16(sk + (uint32_t)(k * CHUNK + off) * 4,
                           mskB + (size_t)k * HWHW + pix0 + off);
            }
        }
        asm volatile("cp.async.commit_group;" ::: "memory");
    };

    prefetch(0, bx);
    prefetch(1, bx + GRIDX);

    int cons = 0, pf = NSTAGE - 1;
    for (int ch = bx; ch < NCHUNK; ch += GRIDX) {
        asm volatile("cp.async.wait_group %0;" :: "n"(NSTAGE - 2) : "memory");
        __syncthreads();
        const float* eb = (const float*)(smraw + cons * STAGE_BYTES);
        const int*   mb = (const int*)(smraw + cons * STAGE_BYTES + EMB_STAGE_FLOATS * 4);

        // each half-warp covers all 128 pixels: lane hl owns pixel-quads hl and hl+16
        const int q0 = hl, q1 = hl + 16;

        // masks for this warp's 4 k-planes, packed as pixel-pairs
        unsigned long long fx0[KPW], fy0[KPW], fx1[KPW], fy1[KPW];
#pragma unroll
        for (int kk = 0; kk < KPW; ++kk) {
            const int4* mrow = (const int4*)(mb + (w * KPW + kk) * CHUNK);
            int4 m0 = mrow[q0];
            int4 m1 = mrow[q1];
            fx0[kk] = pack2(m0.x > 0 ? 1.0f : 0.0f, m0.y > 0 ? 1.0f : 0.0f);
            fy0[kk] = pack2(m0.z > 0 ? 1.0f : 0.0f, m0.w > 0 ? 1.0f : 0.0f);
            fx1[kk] = pack2(m1.x > 0 ? 1.0f : 0.0f, m1.y > 0 ? 1.0f : 0.0f);
            fy1[kk] = pack2(m1.z > 0 ? 1.0f : 0.0f, m1.w > 0 ? 1.0f : 0.0f);
        }

        // s2 partial squares for this half's channels, per pixel-pair slot
        unsigned long long s0x = 0ull, s0y = 0ull, s1x = 0ull, s1y = 0ull;
#pragma unroll
        for (int c = 0; c < CPH; ++c) {
            const ulonglong2* erow = (const ulonglong2*)(eb + (c0 + c) * CHUNK);
            ulonglong2 e0 = erow[q0];
            ulonglong2 e1 = erow[q1];
            fma2(s0x, e0.x, e0.x);
            fma2(s0y, e0.y, e0.y);
            fma2(s1x, e1.x, e1.x);
            fma2(s1y, e1.y, e1.y);
#pragma unroll
            for (int kk = 0; kk < KPW; ++kk) {
                fma2(acc2[kk][c], e0.x, fx0[kk]);
                fma2(acc2[kk][c], e0.y, fy0[kk]);
                fma2(acc2[kk][c], e1.x, fx1[kk]);
                fma2(acc2[kk][c], e1.y, fy1[kk]);
            }
        }
#pragma unroll
        for (int kk = 0; kk < KPW; ++kk) {
            fma2(ssq2[kk], s0x, fx0[kk]);
            fma2(ssq2[kk], s0y, fy0[kk]);
            fma2(ssq2[kk], s1x, fx1[kk]);
            fma2(ssq2[kk], s1y, fy1[kk]);
            add2(cnt2[kk], fx0[kk]);
            add2(cnt2[kk], fy0[kk]);
            add2(cnt2[kk], fx1[kk]);
            add2(cnt2[kk], fy1[kk]);
        }

        prefetch(pf, ch + (NSTAGE - 1) * GRIDX);
        cons = (cons + 1 == NSTAGE) ? 0 : cons + 1;
        pf   = (pf   + 1 == NSTAGE) ? 0 : pf   + 1;
    }

    // ---- reductions + global accumulate ----
#pragma unroll
    for (int kk = 0; kk < KPW; ++kk) {
        const int k = w * KPW + kk;
        // channel sums: reduce within each 16-lane half (channels are half-local)
#pragma unroll
        for (int c = 0; c < CPH; ++c) {
            float v = half_sum_pk(acc2[kk][c]);
            if (hl == 0) atomicAdd(&g_stats[b][k][c0 + c], v);
        }
        // ssq: halves hold disjoint channel contributions -> full-warp sum
        float s = warp_sum(unpack_sum(ssq2[kk]));
        // cnt: both halves counted every pixel -> halve
        float n = warp_sum(unpack_sum(cnt2[kk])) * 0.5f;
        if (l == 0) {
            atomicAdd(&g_stats[b][k][16], s);
            atomicAdd(&g_stats[b][k][17], n);
        }
    }

    // ---- last-block epilogue: compute loss, write out, reset globals ----
    __shared__ bool is_last;
    __threadfence();
    if (tid == 0) {
        unsigned int v = atomicAdd(&g_done, 1u);
        is_last = (v == (unsigned int)(BB * GRIDX) - 1u);
    }
    __syncthreads();
    if (!is_last) return;
    __threadfence();

    float* sh_means = (float*)smraw;                      // [BB][KK][CC] = 1024 floats
    float* sh_pull  = sh_means + BB * KK * CC;
    float* sh_valid = sh_pull + BB * KK;
    float* sh_push  = sh_valid + BB * KK;
    float* sh_pullb = sh_push + BB;
    float* sh_M     = sh_pullb + BB;

    const int t = tid;
    if (t < BB) sh_push[t] = 0.0f;

    if (t < BB * KK) {
        int bb = t >> 4, k = t & 15;
        volatile float* s = g_stats[bb][k];
        float cntv = s[17];
        float ssqv = s[16];
        bool valid = cntv > 0.0f;
        float inv = 1.0f / fmaxf(cntv, 1.0f);
        float dot = 0.0f;
#pragma unroll
        for (int c = 0; c < CC; ++c) {
            float sv = s[c];
            float m = sv * inv;
            sh_means[(bb * KK + k) * CC + c] = m;
            dot = fmaf(sv, m, dot);
        }
        sh_pull[bb * KK + k]  = valid ? (ssqv - dot) / (cntv + 1e-6f) : 0.0f;
        sh_valid[bb * KK + k] = valid ? 1.0f : 0.0f;
    }
    __syncthreads();

    for (int q = t; q < BB * KK * 18; q += NTH)
        ((float*)g_stats)[q] = 0.0f;
    if (t == 0) g_done = 0u;

    if (t < BB) {
        float M = 0.0f, ps = 0.0f;
        for (int k = 0; k < KK; ++k) { M += sh_valid[t * KK + k]; ps += sh_pull[t * KK + k]; }
        sh_M[t]     = M;
        sh_pullb[t] = ps / fmaxf(M, 1.0f);
    }

    float local[BB] = {0.0f, 0.0f, 0.0f, 0.0f};
    for (int idx = t; idx < BB * KK * KK; idx += NTH) {
        int bb = idx >> 8;
        int ij = idx & 255;
        int ii = ij >> 4, jj = ij & 15;
        if (ii < jj && sh_valid[bb * KK + ii] > 0.0f && sh_valid[bb * KK + jj] > 0.0f) {
            float d2 = 0.0f;
#pragma unroll
            for (int c = 0; c < CC; ++c) {
                float d = sh_means[(bb * KK + ii) * CC + c] - sh_means[(bb * KK + jj) * CC + c];
                d2 = fmaf(d, d, d2);
            }
            float dist = sqrtf(d2 + 1e-12f);
            float tm = fmaxf(1.5f - dist, 0.0f);
            local[bb] += tm * tm;
        }
    }
#pragma unroll
    for (int bb = 0; bb < BB; ++bb)
        if (local[bb] != 0.0f) atomicAdd(&sh_push[bb], local[bb]);
    __syncthreads();

    if (t == 0) {
        float loss = 0.0f;
        for (int bb = 0; bb < BB; ++bb) {
            float M = sh_M[bb];
            float npairs = M * (M - 1.0f) * 0.5f;
            float push = (M > 1.0f) ? sh_push[bb] / fmaxf(npairs, 1.0f) : 0.0f;
            loss += 0.5f * sh_pullb[bb] + push;   // DELTA_PULL = 0.5
        }
        out[0] = loss * (1.0f / BB);
    }
}

extern "C" void kernel_launch(void* const* d_in, const int* in_sizes, int n_in,
                              void* d_out, int out_size) {
    const float* emb  = (const float*)d_in[0];
    const int*   mask = (const int*)d_in[1];
    float* out = (float*)d_out;

    cudaFuncSetAttribute(stats_kernel, cudaFuncAttributeMaxDynamicSharedMemorySize, SMEM_BYTES);

    dim3 grid(GRIDX, BB);
    stats_kernel<<<grid, NTH, SMEM_BYTES>>>(emb, mask, out);
}

// round 9
// speedup vs baseline: 1.0555x; 1.0555x over previous
#include <cuda_runtime.h>
#include <cuda_bf16.h>
#include <cstdint>

#define BB 4
#define CC 16
#define KK 16
#define HWHW (512 * 512)          // 262144
#define CHUNK 64                  // pixels per stage
#define NCHUNK (HWHW / CHUNK)     // 4096
#define GRIDX 148                 // 148*4 = 592 blocks = 4/SM, single wave
#define NTH 128
#define KPW 4                     // k's per warp (4 warps x 4 = 16)
#define NSTAGE 6

#define EMB_STAGE_FLOATS (CC * CHUNK)       // 1024 floats = 4 KB
#define MSK_STAGE_INTS   (KK * CHUNK)       // 1024 ints   = 4 KB
#define STAGE_BYTES (EMB_STAGE_FLOATS * 4 + MSK_STAGE_INTS * 4)   // 8 KB
#define SMEM_BYTES (NSTAGE * STAGE_BYTES)   // 48 KB -> 4 blocks/SM

// stats per (b,k): [0..15] channel sums, [16] sum ||e||^2 over fg, [17] count
__device__ float g_stats[BB][KK][18];   // zeroed at load; re-zeroed by last block each launch
__device__ unsigned int g_done;

__device__ __forceinline__ float warp_sum(float x) {
#pragma unroll
    for (int off = 16; off > 0; off >>= 1)
        x += __shfl_down_sync(0xffffffffu, x, off);
    return x;
}
__device__ __forceinline__ void cp_async16(uint32_t dst_smem, const void* src) {
    asm volatile("cp.async.cg.shared.global [%0], [%1], 16;" :: "r"(dst_smem), "l"(src) : "memory");
}

// ---------------- fused kernel ----------------
__global__ __launch_bounds__(NTH, 4)
void stats_kernel(const float* __restrict__ emb, const int* __restrict__ mask,
                  float* __restrict__ out) {
    extern __shared__ char smraw[];

    const int b   = blockIdx.y;
    const int bx  = blockIdx.x;
    const int tid = threadIdx.x;
    const int w   = tid >> 5;
    const int l   = tid & 31;

    const float* embB = emb  + (size_t)b * CC * HWHW;
    const int*   mskB = mask + (size_t)b * KK * HWHW;

    float acc[KPW][CC];
    float ssq[KPW], cnt[KPW];
#pragma unroll
    for (int kk = 0; kk < KPW; ++kk) {
#pragma unroll
        for (int c = 0; c < CC; ++c) acc[kk][c] = 0.0f;
        ssq[kk] = 0.0f; cnt[kk] = 0.0f;
    }

    // per stage: 256 emb + 256 mask 16B units -> 4 cp.async per thread
    auto prefetch = [&](int stage, int ch) {
        if (ch < NCHUNK) {
            const int pix0 = ch * CHUNK;
            uint32_t se = (uint32_t)__cvta_generic_to_shared(smraw + stage * STAGE_BYTES);
            uint32_t sk = se + EMB_STAGE_FLOATS * 4;
#pragma unroll
            for (int j = 0; j < 2; ++j) {
                int u   = tid + j * NTH;        // 0..255
                int c   = u >> 4;               // channel (16 16B units per 64-float row)
                int off = (u & 15) << 2;        // float offset within row
                cp_async16(se + (uint32_t)(c * CHUNK + off) * 4,
                           embB + (size_t)c * HWHW + pix0 + off);
            }
#pragma unroll
            for (int j = 0; j < 2; ++j) {
                int u   = tid + j * NTH;
                int k   = u >> 4;
                int off = (u & 15) << 2;
                cp_async16(sk + (uint32_t)(k * CHUNK + off) * 4,
                           mskB + (size_t)k * HWHW + pix0 + off);
            }
        }
        asm volatile("cp.async.commit_group;" ::: "memory");
    };

    // fill NSTAGE-1 stages -> up to 5 groups in flight per block
#pragma unroll
    for (int s = 0; s < NSTAGE - 1; ++s)
        prefetch(s, bx + s * GRIDX);

    int cons = 0, pf = NSTAGE - 1;
    for (int ch = bx; ch < NCHUNK; ch += GRIDX) {
        asm volatile("cp.async.wait_group %0;" :: "n"(NSTAGE - 2) : "memory");
        __syncthreads();
        const float* eb = (const float*)(smraw + cons * STAGE_BYTES);
        const int*   mb = (const int*)(smraw + cons * STAGE_BYTES + EMB_STAGE_FLOATS * 4);

        // lane l owns pixels {2l, 2l+1}; masks are exactly 0/1 -> direct I2F
        float mf[KPW][2];
#pragma unroll
        for (int kk = 0; kk < KPW; ++kk) {
            int2 m = ((const int2*)(mb + (w * KPW + kk) * CHUNK))[l];
            mf[kk][0] = (float)m.x;
            mf[kk][1] = (float)m.y;
        }

        float s2a = 0.0f, s2b = 0.0f;
#pragma unroll
        for (int c = 0; c < CC; ++c) {
            float2 e = ((const float2*)(eb + c * CHUNK))[l];
            s2a = fmaf(e.x, e.x, s2a);
            s2b = fmaf(e.y, e.y, s2b);
#pragma unroll
            for (int kk = 0; kk < KPW; ++kk) {
                float a = acc[kk][c];
                a = fmaf(e.x, mf[kk][0], a);
                a = fmaf(e.y, mf[kk][1], a);
                acc[kk][c] = a;
            }
        }
#pragma unroll
        for (int kk = 0; kk < KPW; ++kk) {
            float s = ssq[kk];
            s = fmaf(s2a, mf[kk][0], s);
            s = fmaf(s2b, mf[kk][1], s);
            ssq[kk] = s;
            cnt[kk] += mf[kk][0] + mf[kk][1];
        }

        // prefetch targets the stage consumed LAST iteration; all warps passed
        // this iteration's top barrier after finishing that read -> safe
        prefetch(pf, ch + (NSTAGE - 1) * GRIDX);
        cons = (cons + 1 == NSTAGE) ? 0 : cons + 1;
        pf   = (pf   + 1 == NSTAGE) ? 0 : pf   + 1;
    }

    // ---- warp reduce + global accumulate ----
#pragma unroll
    for (int kk = 0; kk < KPW; ++kk) {
        const int k = w * KPW + kk;
#pragma unroll
        for (int c = 0; c < CC; ++c) {
            float v = warp_sum(acc[kk][c]);
            if (l == 0) atomicAdd(&g_stats[b][k][c], v);
        }
        float s = warp_sum(ssq[kk]);
        float n = warp_sum(cnt[kk]);
        if (l == 0) {
            atomicAdd(&g_stats[b][k][16], s);
            atomicAdd(&g_stats[b][k][17], n);
        }
    }

    // ---- last-block epilogue: compute loss, write out, reset globals ----
    __shared__ bool is_last;
    __threadfence();
    if (tid == 0) {
        unsigned int v = atomicAdd(&g_done, 1u);
        is_last = (v == (unsigned int)(BB * GRIDX) - 1u);
    }
    __syncthreads();
    if (!is_last) return;
    __threadfence();

    float* sh_means = (float*)smraw;                      // [BB][KK][CC] = 1024 floats
    float* sh_pull  = sh_means + BB * KK * CC;
    float* sh_valid = sh_pull + BB * KK;
    float* sh_push  = sh_valid + BB * KK;
    float* sh_pullb = sh_push + BB;
    float* sh_M     = sh_pullb + BB;

    const int t = tid;
    if (t < BB) sh_push[t] = 0.0f;

    if (t < BB * KK) {
        int bb = t >> 4, k = t & 15;
        volatile float* s = g_stats[bb][k];
        float cntv = s[17];
        float ssqv = s[16];
        bool valid = cntv > 0.0f;
        float inv = 1.0f / fmaxf(cntv, 1.0f);
        float dot = 0.0f;
#pragma unroll
        for (int c = 0; c < CC; ++c) {
            float sv = s[c];
            float m = sv * inv;
            sh_means[(bb * KK + k) * CC + c] = m;
            dot = fmaf(sv, m, dot);
        }
        sh_pull[bb * KK + k]  = valid ? (ssqv - dot) / (cntv + 1e-6f) : 0.0f;
        sh_valid[bb * KK + k] = valid ? 1.0f : 0.0f;
    }
    __syncthreads();

    for (int q = t; q < BB * KK * 18; q += NTH)
        ((float*)g_stats)[q] = 0.0f;
    if (t == 0) g_done = 0u;

    if (t < BB) {
        float M = 0.0f, ps = 0.0f;
        for (int k = 0; k < KK; ++k) { M += sh_valid[t * KK + k]; ps += sh_pull[t * KK + k]; }
        sh_M[t]     = M;
        sh_pullb[t] = ps / fmaxf(M, 1.0f);
    }

    float local[BB] = {0.0f, 0.0f, 0.0f, 0.0f};
    for (int idx = t; idx < BB * KK * KK; idx += NTH) {
        int bb = idx >> 8;
        int ij = idx & 255;
        int ii = ij >> 4, jj = ij & 15;
        if (ii < jj && sh_valid[bb * KK + ii] > 0.0f && sh_valid[bb * KK + jj] > 0.0f) {
            float d2 = 0.0f;
#pragma unroll
            for (int c = 0; c < CC; ++c) {
                float d = sh_means[(bb * KK + ii) * CC + c] - sh_means[(bb * KK + jj) * CC + c];
                d2 = fmaf(d, d, d2);
            }
            float dist = sqrtf(d2 + 1e-12f);
            float tm = fmaxf(1.5f - dist, 0.0f);
            local[bb] += tm * tm;
        }
    }
#pragma unroll
    for (int bb = 0; bb < BB; ++bb)
        if (local[bb] != 0.0f) atomicAdd(&sh_push[bb], local[bb]);
    __syncthreads();

    if (t == 0) {
        float loss = 0.0f;
        for (int bb = 0; bb < BB; ++bb) {
            float M = sh_M[bb];
            float npairs = M * (M - 1.0f) * 0.5f;
            float push = (M > 1.0f) ? sh_push[bb] / fmaxf(npairs, 1.0f) : 0.0f;
            loss += 0.5f * sh_pullb[bb] + push;   // DELTA_PULL = 0.5
        }
        out[0] = loss * (1.0f / BB);
    }
}

extern "C" void kernel_launch(void* const* d_in, const int* in_sizes, int n_in,
                              void* d_out, int out_size) {
    const float* emb  = (const float*)d_in[0];
    const int*   mask = (const int*)d_in[1];
    float* out = (float*)d_out;

    cudaFuncSetAttribute(stats_kernel, cudaFuncAttributeMaxDynamicSharedMemorySize, SMEM_BYTES);

    dim3 grid(GRIDX, BB);
    stats_kernel<<<grid, NTH, SMEM_BYTES>>>(emb, mask, out);
}